// round 10
// baseline (speedup 1.0000x reference)
#include <cuda_runtime.h>
#include <cuda_fp16.h>
#include <cstdint>

#define BB 64
#define TT 1500
#define FF 36
#define HH 512
#define NT 256          // 8 warps: ks2 x mt4; each warp covers n=32 (8 units x 4 gates)
#define GRID 128        // 64 CTAs per layer, 8 units per CTA

// ---------------- device globals ----------------
__device__ float g_xg0p[(size_t)TT * 131072];   // 786MB acc-init [t][c64][tl128][q4][e4]
__device__ float g_b2p[64 * 2048];              // layer2 bias  [c][tl128][q4][e4]
__device__ uint32_t g_wf1[64 * 8192];           // layer1 B-frags [c][kt32][p2][lane32][e4]
__device__ uint32_t g_wf2[64 * 16384];          // layer2 B-frags [c][kt64][p2][lane32][e4]
__device__ uint32_t g_h1s[4 * 16384];           // h1 ring, fp16 A-frag layout [kt32][mt4][lane32][reg4]
__device__ uint32_t g_h2s[2 * 16384];           // h2 ring
// 4 group counters per (layer, step): group g = producer CTAs [16g,16g+16) = A kt range [8g, 8g+8)
struct alignas(128) FlagG { unsigned g[4]; unsigned pad[28]; };
__device__ FlagG g_f1[TT + 2];
__device__ FlagG g_f2[TT + 2];

// ---------------- helpers ----------------
__device__ __forceinline__ float tanha(float x) {
    float y;
    asm("tanh.approx.f32 %0, %1;" : "=f"(y) : "f"(x));
    return y;
}
__device__ __forceinline__ float sigm(float x) { return fmaf(tanha(0.5f * x), 0.5f, 0.5f); }

__device__ __forceinline__ uint32_t f2h2(float lo, float hi) {
    __half2 h = __floats2half2_rn(lo, hi);
    return *reinterpret_cast<uint32_t*>(&h);
}

__device__ __forceinline__ void mma16(float* d, uint4 a, uint32_t b0, uint32_t b1) {
    asm volatile(
        "mma.sync.aligned.m16n8k16.row.col.f32.f16.f16.f32 "
        "{%0,%1,%2,%3},{%4,%5,%6,%7},{%8,%9},{%0,%1,%2,%3};\n"
        : "+f"(d[0]), "+f"(d[1]), "+f"(d[2]), "+f"(d[3])
        : "r"(a.x), "r"(a.y), "r"(a.z), "r"(a.w), "r"(b0), "r"(b1));
}

// all lanes of the calling warp spin on one flag word (single coalesced L2 req per poll)
__device__ __forceinline__ void waitflag(const unsigned* p, unsigned tgt) {
    unsigned v;
    do {
        asm volatile("ld.acquire.gpu.global.u32 %0, [%1];" : "=r"(v) : "l"(p) : "memory");
    } while (v < tgt);
}
// wait until ALL 4 groups reach tgt (used for backpressure, off critical path)
__device__ __forceinline__ void waitflag4(const FlagG* f, unsigned tgt) {
    unsigned a, b, c, d;
    do {
        asm volatile("ld.acquire.gpu.global.u32 %0, [%1];" : "=r"(a) : "l"(&f->g[0]) : "memory");
        asm volatile("ld.acquire.gpu.global.u32 %0, [%1];" : "=r"(b) : "l"(&f->g[1]) : "memory");
        asm volatile("ld.acquire.gpu.global.u32 %0, [%1];" : "=r"(c) : "l"(&f->g[2]) : "memory");
        asm volatile("ld.acquire.gpu.global.u32 %0, [%1];" : "=r"(d) : "l"(&f->g[3]) : "memory");
    } while (a < tgt || b < tgt || c < tgt || d < tgt);
}

// 8 k16-tiles: per kt: 1 LDG.128 (A) + 2 LDS.128 (B, 4 n-tiles) + 4 MMA.
__device__ __forceinline__ void gemm8(float acc[4][4], const uint4* __restrict__ Ap,
                                      const uint4* __restrict__ Bp) {
    uint4 aq[8];
#pragma unroll
    for (int i = 0; i < 8; i++) aq[i] = __ldcg(Ap + i * 128);
#pragma unroll
    for (int i = 0; i < 8; i++) {
        uint4 av = aq[i];
        uint4 q1 = Bp[i * 64];
        uint4 q2 = Bp[i * 64 + 32];
        mma16(acc[0], av, q1.x, q1.y);
        mma16(acc[1], av, q1.z, q1.w);
        mma16(acc[2], av, q2.x, q2.y);
        mma16(acc[3], av, q2.z, q2.w);
    }
}

// ---------------- setup kernels ----------------
__global__ void reset_kernel() {
    int idx = blockIdx.x * 256 + threadIdx.x;
    if (idx < TT + 2) {
#pragma unroll
        for (int j = 0; j < 4; j++) {
            g_f1[idx].g[j] = (idx == 0) ? 16u : 0u;
            g_f2[idx].g[j] = (idx == 0) ? 16u : 0u;
        }
    }
    if (idx < 16384) {
        g_h1s[3 * 16384 + idx] = 0u;   // h1[-1] slab ((-1)&3 = 3)
        g_h2s[16384 + idx] = 0u;       // h2[-1] slab ((-1)&1 = 1)
    }
}

// B-fragment value for (c, kt-global within source W, p, lane, e):
//   nt = 2p + (e>>1); gate = (nt&1)*2 + (gid&1); u = c*8 + (nt>>1)*4 + (gid>>1)
//   row = gate*512 + u; k = kt*16 + (e&1)*8 + tig*2
__global__ void pack_kernel(const float* __restrict__ Whh0, const float* __restrict__ Wih1,
                            const float* __restrict__ Whh1, const float* __restrict__ bih1,
                            const float* __restrict__ bhh1) {
    int cb = blockIdx.x;
    if (cb < 64) {
        int c = cb;
        uint32_t* dst = g_wf1 + c * 8192;
        for (int idx = threadIdx.x; idx < 8192; idx += 256) {
            int e = idx & 3, lane = (idx >> 2) & 31, p = (idx >> 7) & 1, kt = idx >> 8;
            int gid = lane >> 2, tig = lane & 3;
            int nt = 2 * p + (e >> 1);
            int gate = (nt & 1) * 2 + (gid & 1);
            int u = c * 8 + (nt >> 1) * 4 + (gid >> 1);
            int row = gate * 512 + u;
            int k = kt * 16 + (e & 1) * 8 + tig * 2;
            dst[idx] = f2h2(Whh0[row * HH + k], Whh0[row * HH + k + 1]);
        }
    } else {
        int c = cb - 64;
        uint32_t* dst = g_wf2 + c * 16384;
        for (int idx = threadIdx.x; idx < 16384; idx += 256) {
            int e = idx & 3, lane = (idx >> 2) & 31, p = (idx >> 7) & 1, kt = idx >> 8;
            int gid = lane >> 2, tig = lane & 3;
            int nt = 2 * p + (e >> 1);
            int gate = (nt & 1) * 2 + (gid & 1);
            int u = c * 8 + (nt >> 1) * 4 + (gid >> 1);
            int row = gate * 512 + u;
            float v0, v1;
            if (kt < 32) {
                int k = kt * 16 + (e & 1) * 8 + tig * 2;
                v0 = Wih1[row * HH + k]; v1 = Wih1[row * HH + k + 1];
            } else {
                int k = (kt - 32) * 16 + (e & 1) * 8 + tig * 2;
                v0 = Whh1[row * HH + k]; v1 = Whh1[row * HH + k + 1];
            }
            dst[idx] = f2h2(v0, v1);
        }
        // bias in acc-slot layout: [tl128][q4][e4]; gate=(q&1)*2+(e&1); u=c*8+(q>>1)*4+tig
        for (int idx = threadIdx.x; idx < 2048; idx += 256) {
            int e = idx & 3, q = (idx >> 2) & 3, tl = idx >> 4;
            int tig = tl & 3;
            int u = c * 8 + (q >> 1) * 4 + tig;
            int gate = (q & 1) * 2 + (e & 1);
            int row = gate * 512 + u;
            g_b2p[c * 2048 + idx] = bih1[row] + bhh1[row];
        }
    }
}

// acc-init for layer1 in the same acc-slot layout
__global__ void xg0_kernel(const float* __restrict__ x, const float* __restrict__ Wih0,
                           const float* __restrict__ bih0, const float* __restrict__ bhh0) {
    __shared__ float ws[32][40];    // rows rl = gate*8 + uloc
    __shared__ float gsm[64][33];   // [b][rl]
    __shared__ float bsm[32];
    int t = blockIdx.x >> 6, c = blockIdx.x & 63;
    int tid = threadIdx.x;
    for (int i = tid; i < 32 * FF; i += 256) {
        int rl = i / FF, f = i - rl * FF;
        int row = (rl >> 3) * 512 + c * 8 + (rl & 7);
        ws[rl][f] = Wih0[row * FF + f];
    }
    if (tid < 32) {
        int rl = tid;
        int row = (rl >> 3) * 512 + c * 8 + (rl & 7);
        bsm[rl] = bih0[row] + bhh0[row];
    }
    __syncthreads();
    {   // phase A: outer product, x in registers, ws broadcast per warp
        int b = tid & 63, rq = tid >> 6;
        float xr[36];
        const float4* xp = (const float4*)(x + ((size_t)b * TT + t) * FF);
#pragma unroll
        for (int f4 = 0; f4 < 9; f4++) {
            float4 v = __ldg(xp + f4);
            xr[f4 * 4] = v.x; xr[f4 * 4 + 1] = v.y; xr[f4 * 4 + 2] = v.z; xr[f4 * 4 + 3] = v.w;
        }
#pragma unroll
        for (int jr = 0; jr < 8; jr++) {
            int rl = rq * 8 + jr;
            const float4* wp = (const float4*)(&ws[rl][0]);
            float a = 0.f;
#pragma unroll
            for (int f4 = 0; f4 < 9; f4++) {
                float4 w = wp[f4];
                a = fmaf(xr[f4 * 4], w.x, a);
                a = fmaf(xr[f4 * 4 + 1], w.y, a);
                a = fmaf(xr[f4 * 4 + 2], w.z, a);
                a = fmaf(xr[f4 * 4 + 3], w.w, a);
            }
            gsm[b][rl] = a;
        }
    }
    __syncthreads();
    {   // phase B: acc-slot packing (2 quads per thread)
        int hq = tid >> 7, tl = tid & 127;
        int mtb = tl >> 5, lane = tl & 31;
        int gid = lane >> 2, tig = lane & 3;
        float v[8];
#pragma unroll
        for (int qq = 0; qq < 2; qq++) {
            int q = hq * 2 + qq;
            int uloc = (q >> 1) * 4 + tig;
#pragma unroll
            for (int e = 0; e < 4; e++) {
                int gate = (q & 1) * 2 + (e & 1);
                int b = mtb * 16 + gid + 8 * (e >> 1);
                v[qq * 4 + e] = bsm[gate * 8 + uloc] + gsm[b][gate * 8 + uloc];
            }
        }
        size_t off = (size_t)t * 131072 + c * 2048 + tl * 16 + hq * 8;
        float4* op = (float4*)(g_xg0p + off);
        op[0] = make_float4(v[0], v[1], v[2], v[3]);
        op[1] = make_float4(v[4], v[5], v[6], v[7]);
    }
}

// ---------------- persistent 2-layer LSTM ----------------
// smem: Bs uint4[4096] (64KB weights) + EX float4[512] (8KB k-split handoff)
#define SMEM_BYTES 73728

__global__ void __launch_bounds__(NT, 1) lstm_kernel() {
    extern __shared__ uint4 smemu[];
    uint4* Bs = smemu;
    float4* EX = (float4*)(smemu + 4096);

    const int cta = blockIdx.x;
    const int layer = cta >> 6;
    const int c = cta & 63;
    const int tid = threadIdx.x;
    const int ks = tid >> 7;               // k-split group
    const int tl = tid & 127;
    const int mt = (tid >> 5) & 3;
    const int lane = tid & 31;
    const int gid = lane >> 2, tig = lane & 3;

    {   // weights -> smem (fragment-packed)
        const uint4* wsrc = (const uint4*)(layer ? (g_wf2 + c * 16384) : (g_wf1 + c * 8192));
        int tot = layer ? 4096 : 2048;
        for (int i = tid; i < tot; i += NT) Bs[i] = wsrc[i];
    }
    float bias16[16];
    if (layer && ks == 0) {
        const float4* bp = (const float4*)(g_b2p + c * 2048 + tl * 16);
#pragma unroll
        for (int q = 0; q < 4; q++) {
            float4 v = bp[q];
            bias16[q * 4] = v.x; bias16[q * 4 + 1] = v.y;
            bias16[q * 4 + 2] = v.z; bias16[q * 4 + 3] = v.w;
        }
    }
    float cst[4] = {0.f, 0.f, 0.f, 0.f};
    __syncthreads();

    // h-store addressing (ks0 threads): units u1=c*8+tig, u2=c*8+4+tig; batches mt*16+gid, +8
    const int ktS = c >> 1;
    const int sbase = ((ktS * 4 + mt) * 32 + gid * 4 + (tig >> 1)) * 4 + 2 * (c & 1);
    const int half = tig & 1;
    const int myGrp = c >> 4;              // producer flag group

    for (int t = 0; t < TT; t++) {
        float acc[4][4];
        if (!layer) {
            float4 xg[4];
            if (ks == 0) {
                const float4* xp = (const float4*)(g_xg0p + (size_t)t * 131072 + c * 2048 + tl * 16);
#pragma unroll
                for (int q = 0; q < 4; q++) xg[q] = __ldcg(xp + q);
            }
            if (t >= 4) waitflag4(&g_f2[t - 3], 16);   // ring-overwrite backpressure (usually set)
            if (ks == 0) {
#pragma unroll
                for (int q = 0; q < 4; q++) {
                    acc[q][0] = xg[q].x; acc[q][1] = xg[q].y;
                    acc[q][2] = xg[q].z; acc[q][3] = xg[q].w;
                }
            } else {
#pragma unroll
                for (int i = 0; i < 16; i++) acc[i >> 2][i & 3] = 0.f;
            }
            // chunked GEMM over h1[t-1]: per-warp wait only the needed producer group
            const uint4* Ap = (const uint4*)(g_h1s + ((t - 1) & 3) * 16384) + ks * 2048 + mt * 32 + lane;
#pragma unroll
            for (int ch = 0; ch < 2; ch++) {
                waitflag(&g_f1[t].g[ks * 2 + ch], 16);
                gemm8(acc, Ap + ch * 1024, Bs + ks * 1024 + ch * 512 + lane);
            }
        } else {
            if (ks == 0) {
#pragma unroll
                for (int i = 0; i < 16; i++) acc[i >> 2][i & 3] = bias16[i];
            } else {
#pragma unroll
                for (int i = 0; i < 16; i++) acc[i >> 2][i & 3] = 0.f;
            }
            // W_ih1 part over h1[t] (layer1 runs ahead -> waits ~0)
            const uint4* Ap1 = (const uint4*)(g_h1s + (t & 3) * 16384) + ks * 2048 + mt * 32 + lane;
#pragma unroll
            for (int ch = 0; ch < 2; ch++) {
                waitflag(&g_f1[t + 1].g[ks * 2 + ch], 16);
                gemm8(acc, Ap1 + ch * 1024, Bs + ks * 1024 + ch * 512 + lane);
            }
            // W_hh1 part over h2[t-1] — the serial dependence, chunked to hide producer spread
            const uint4* Ap2 = (const uint4*)(g_h2s + ((t - 1) & 1) * 16384) + ks * 2048 + mt * 32 + lane;
#pragma unroll
            for (int ch = 0; ch < 2; ch++) {
                waitflag(&g_f2[t].g[ks * 2 + ch], 16);
                gemm8(acc, Ap2 + ch * 1024, Bs + 2048 + ks * 1024 + ch * 512 + lane);
            }
        }
        // k-split handoff: ks1 ships partials; ks0 reduces, does cell + h store
        if (ks == 1) {
#pragma unroll
            for (int q = 0; q < 4; q++)
                EX[tl * 4 + q] = make_float4(acc[q][0], acc[q][1], acc[q][2], acc[q][3]);
        }
        __syncthreads();
        uint32_t* slab = layer ? (g_h2s + (t & 1) * 16384) : (g_h1s + (t & 3) * 16384);
        if (ks == 0) {
#pragma unroll
            for (int q = 0; q < 4; q++) {
                float4 v = EX[tl * 4 + q];
                acc[q][0] += v.x; acc[q][1] += v.y; acc[q][2] += v.z; acc[q][3] += v.w;
            }
            uint16_t* hp = (uint16_t*)slab;
#pragma unroll
            for (int uu = 0; uu < 2; uu++) {
#pragma unroll
                for (int bb = 0; bb < 2; bb++) {
                    float iv = sigm(acc[uu * 2][bb * 2]);
                    float fv = sigm(acc[uu * 2][bb * 2 + 1]);
                    float gv = tanha(acc[uu * 2 + 1][bb * 2]);
                    float ov = sigm(acc[uu * 2 + 1][bb * 2 + 1]);
                    int ci = uu * 2 + bb;
                    float cv = fmaf(fv, cst[ci], iv * gv);
                    cst[ci] = cv;
                    float hv = ov * tanha(cv);
                    __half hh = __float2half_rn(hv);
                    hp[(sbase + uu * 8 + bb) * 2 + half] = __half_as_ushort(hh);
                }
            }
        }
        __syncthreads();
        if (tid == 0) {
            unsigned* fp = layer ? &g_f2[t + 1].g[myGrp] : &g_f1[t + 1].g[myGrp];
            asm volatile("red.release.gpu.global.add.u32 [%0], 1;" ::"l"(fp) : "memory");
        }
    }
}

// ---------------- final projection ----------------
__global__ void out_kernel(const float* __restrict__ Wout, const float* __restrict__ bout,
                           float* __restrict__ out) {
    __shared__ float hs[512];
    int b = blockIdx.x;
    const uint32_t* slab = g_h2s + ((TT - 1) & 1) * 16384;
    for (int k = threadIdx.x; k < 512; k += 64) {
        int kt = k >> 4, ku = k & 15, mtb = b >> 4, r = b & 15;
        int laneS = (r & 7) * 4 + ((ku & 7) >> 1);
        int reg = (r >> 3) + 2 * (ku >> 3);
        uint32_t v = slab[((kt * 4 + mtb) * 32 + laneS) * 4 + reg];
        __half2 h2v = *reinterpret_cast<__half2*>(&v);
        hs[k] = (ku & 1) ? __high2float(h2v) : __low2float(h2v);
    }
    __syncthreads();
    int o = threadIdx.x;
    float acc = bout[o];
    const float* wr = Wout + o * HH;
#pragma unroll 8
    for (int k = 0; k < HH; k++) acc = fmaf(hs[k], wr[k], acc);
    out[b * 64 + o] = acc;
}

// ---------------- launch ----------------
extern "C" void kernel_launch(void* const* d_in, const int* in_sizes, int n_in,
                              void* d_out, int out_size) {
    const float* x    = (const float*)d_in[0];
    const float* Wih0 = (const float*)d_in[1];
    const float* Whh0 = (const float*)d_in[2];
    const float* bih0 = (const float*)d_in[3];
    const float* bhh0 = (const float*)d_in[4];
    const float* Wih1 = (const float*)d_in[5];
    const float* Whh1 = (const float*)d_in[6];
    const float* bih1 = (const float*)d_in[7];
    const float* bhh1 = (const float*)d_in[8];
    const float* Wout = (const float*)d_in[9];
    const float* bout = (const float*)d_in[10];
    float* out = (float*)d_out;

    cudaFuncSetAttribute(lstm_kernel, cudaFuncAttributeMaxDynamicSharedMemorySize, SMEM_BYTES);

    reset_kernel<<<64, 256>>>();
    pack_kernel<<<128, 256>>>(Whh0, Wih1, Whh1, bih1, bhh1);
    xg0_kernel<<<TT * 64, 256>>>(x, Wih0, bih0, bhh0);
    lstm_kernel<<<GRID, NT, SMEM_BYTES>>>();
    out_kernel<<<64, 64>>>(Wout, bout, out);
}